// round 1
// baseline (speedup 1.0000x reference)
#include <cuda_runtime.h>
#include <cuda_bf16.h>

#define BATCH   2
#define CCH     64
#define NTOK    110592      // 48*48*48
#define HEADS   4
#define DHEAD   32
#define NCH     144         // chunks per batch
#define CHUNK   768         // columns per chunk (144*768 = 110592)
#define SUB     128         // columns per smem subtile
#define XSTR    68          // padded stride for x subtile (floats, 16B-aligned rows)
#define CB      108         // column blocks in kernel 3 (108*1024 = 110592)

// Scratch (no allocations allowed in kernel_launch)
__device__ float g_ctx_part[BATCH * NCH * HEADS * DHEAD * DHEAD]; // [b][j][h*32+d][e]
__device__ float g_s_part[BATCH * NCH * HEADS * DHEAD];           // [b][j][h*32+d]
__device__ float g_M[BATCH * CCH * CCH];                          // [b][c1][c2]

// ---------------------------------------------------------------------------
// Kernel 1: stream x, compute k=Wk*x, v=Wv*x per column, accumulate
// unnormalized ctx partial = sum_n exp(k_d) * v_e  and  s_d = sum_n exp(k_d).
// 4 warps per block, warp w = head w. Lane d owns k/v row (w*32+d).
// Weights live in registers (64+64 floats per lane).
// ---------------------------------------------------------------------------
__global__ void __launch_bounds__(128, 2)
kv_ctx_kernel(const float* __restrict__ x, const float* __restrict__ wqkv)
{
    const int blk  = blockIdx.x;
    const int b    = blk / NCH;
    const int j    = blk - b * NCH;
    const int tid  = threadIdx.x;
    const int w    = tid >> 5;     // head
    const int lane = tid & 31;     // d

    __shared__ __align__(16) float xs[SUB * XSTR];            // x subtile, [col][c], padded
    __shared__ __align__(16) float vbuf[2][HEADS][4][DHEAD];  // v staging, double-buffered

    // Load this lane's K/V weight rows into registers
    float wk[64], wv[64];
    {
        const float4* kr = reinterpret_cast<const float4*>(wqkv + (size_t)(128 + w * 32 + lane) * 64);
        const float4* vr = reinterpret_cast<const float4*>(wqkv + (size_t)(256 + w * 32 + lane) * 64);
#pragma unroll
        for (int i = 0; i < 16; ++i) {
            float4 a = kr[i];
            wk[4*i+0] = a.x; wk[4*i+1] = a.y; wk[4*i+2] = a.z; wk[4*i+3] = a.w;
            float4 c = vr[i];
            wv[4*i+0] = c.x; wv[4*i+1] = c.y; wv[4*i+2] = c.z; wv[4*i+3] = c.w;
        }
    }

    float ctx[DHEAD];
#pragma unroll
    for (int e = 0; e < DHEAD; ++e) ctx[e] = 0.f;
    float ssum = 0.f;

    const float* xb = x + (size_t)b * CCH * NTOK + (size_t)j * CHUNK;
    int par = 0;

    for (int st = 0; st < CHUNK / SUB; ++st) {
        __syncthreads();  // guard previous subtile reads
        const float* xsub = xb + st * SUB;
        // cooperative load: thread tid owns column tid of the subtile
#pragma unroll 4
        for (int c = 0; c < CCH; ++c)
            xs[tid * XSTR + c] = xsub[(size_t)c * NTOK + tid];
        __syncthreads();

        for (int jb = 0; jb < SUB; jb += 4) {
            float kk[4] = {0.f, 0.f, 0.f, 0.f};
            float vv[4] = {0.f, 0.f, 0.f, 0.f};
            const float* xrow = xs + jb * XSTR;
#pragma unroll
            for (int c4 = 0; c4 < 16; ++c4) {
#pragma unroll
                for (int jj = 0; jj < 4; ++jj) {
                    float4 xv = *reinterpret_cast<const float4*>(xrow + jj * XSTR + c4 * 4);
                    kk[jj] = fmaf(wk[4*c4+0], xv.x, kk[jj]);
                    kk[jj] = fmaf(wk[4*c4+1], xv.y, kk[jj]);
                    kk[jj] = fmaf(wk[4*c4+2], xv.z, kk[jj]);
                    kk[jj] = fmaf(wk[4*c4+3], xv.w, kk[jj]);
                    vv[jj] = fmaf(wv[4*c4+0], xv.x, vv[jj]);
                    vv[jj] = fmaf(wv[4*c4+1], xv.y, vv[jj]);
                    vv[jj] = fmaf(wv[4*c4+2], xv.z, vv[jj]);
                    vv[jj] = fmaf(wv[4*c4+3], xv.w, vv[jj]);
                }
            }
            float pp[4];
#pragma unroll
            for (int jj = 0; jj < 4; ++jj) {
                pp[jj] = __expf(kk[jj]);     // no max needed: |k| ~ O(6)
                ssum += pp[jj];
                vbuf[par][w][jj][lane] = vv[jj];
            }
            __syncwarp();
            // ctx[e] += p_d(col) * v_e(col), v broadcast via smem
#pragma unroll
            for (int e4 = 0; e4 < 8; ++e4) {
#pragma unroll
                for (int jj = 0; jj < 4; ++jj) {
                    float4 vb = *reinterpret_cast<const float4*>(&vbuf[par][w][jj][e4 * 4]);
                    ctx[4*e4+0] = fmaf(pp[jj], vb.x, ctx[4*e4+0]);
                    ctx[4*e4+1] = fmaf(pp[jj], vb.y, ctx[4*e4+1]);
                    ctx[4*e4+2] = fmaf(pp[jj], vb.z, ctx[4*e4+2]);
                    ctx[4*e4+3] = fmaf(pp[jj], vb.w, ctx[4*e4+3]);
                }
            }
            par ^= 1;
        }
    }

    // Write chunk partials
    {
        size_t base = (((size_t)(b * NCH + j) * HEADS + w) * DHEAD + lane) * DHEAD;
#pragma unroll
        for (int e4 = 0; e4 < 8; ++e4) {
            float4 v4 = make_float4(ctx[4*e4+0], ctx[4*e4+1], ctx[4*e4+2], ctx[4*e4+3]);
            *reinterpret_cast<float4*>(&g_ctx_part[base + 4 * e4]) = v4;
        }
        g_s_part[((size_t)(b * NCH + j) * HEADS + w) * DHEAD + lane] = ssum;
    }
}

// ---------------------------------------------------------------------------
// Kernel 2: reduce chunk partials -> ctx (normalized), then
// M[b] = Wout @ blockdiag_h(ctx_h^T) @ Wq   (64x64 per batch). One block/batch.
// ---------------------------------------------------------------------------
__global__ void __launch_bounds__(256)
reduce_proj_kernel(const float* __restrict__ wqkv, const float* __restrict__ wout)
{
    const int b   = blockIdx.x;
    const int tid = threadIdx.x;
    __shared__ float ctxs[HEADS * DHEAD * DHEAD]; // [h*32+d][e]  (4096)
    __shared__ float ssum[HEADS * DHEAD];         // 128
    __shared__ float Ts[128 * 64];                // T[o][c], o = h*32+e

    for (int idx = tid; idx < 4096; idx += 256) {
        float acc = 0.f;
        const float* p = g_ctx_part + (size_t)b * NCH * 4096 + idx;
        for (int jj = 0; jj < NCH; ++jj) acc += p[(size_t)jj * 4096];
        ctxs[idx] = acc;
    }
    if (tid < 128) {
        float acc = 0.f;
        const float* p = g_s_part + (size_t)b * NCH * 128 + tid;
        for (int jj = 0; jj < NCH; ++jj) acc += p[jj * 128];
        ssum[tid] = acc;
    }
    __syncthreads();
    for (int idx = tid; idx < 4096; idx += 256)
        ctxs[idx] = ctxs[idx] / ssum[idx >> 5];   // normalize row (h,d)
    __syncthreads();

    // T[h*32+e][c] = sum_d ctx[h][d][e] * Wq[h*32+d][c]
    for (int idx = tid; idx < 128 * 64; idx += 256) {
        const int o = idx >> 6, c = idx & 63;
        const int h = o >> 5, e = o & 31;
        float acc = 0.f;
#pragma unroll 8
        for (int d = 0; d < 32; ++d)
            acc = fmaf(ctxs[(h * 32 + d) * 32 + e], wqkv[(size_t)(h * 32 + d) * 64 + c], acc);
        Ts[idx] = acc;
    }
    __syncthreads();

    // M[c1][c2] = sum_o Wout[c1][o] * T[o][c2]
    for (int idx = tid; idx < 4096; idx += 256) {
        const int c1 = idx >> 6, c2 = idx & 63;
        float acc = 0.f;
#pragma unroll 8
        for (int o = 0; o < 128; ++o)
            acc = fmaf(wout[(size_t)c1 * 128 + o], Ts[o * 64 + c2], acc);
        g_M[(size_t)b * 4096 + idx] = acc;
    }
}

// ---------------------------------------------------------------------------
// Kernel 3: out[b][c][n] = sum_c' M[b][c][c'] * x[b][c'][n] + b_out[c]
// ---------------------------------------------------------------------------
__global__ void __launch_bounds__(256, 2)
out_proj_kernel(const float* __restrict__ x, const float* __restrict__ bout,
                float* __restrict__ out)
{
    const int blk = blockIdx.x;
    const int b   = blk / CB;
    const int jc  = blk - b * CB;
    const int tid = threadIdx.x;
    __shared__ __align__(16) float Ms[CCH * CCH];
    __shared__ float bo[CCH];
    for (int i = tid; i < 4096; i += 256) Ms[i] = g_M[(size_t)b * 4096 + i];
    if (tid < 64) bo[tid] = bout[tid];
    __syncthreads();

    const float* xb = x   + (size_t)b * CCH * NTOK;
    float*       ob = out + (size_t)b * CCH * NTOK;

    for (int it = 0; it < 4; ++it) {
        const int n = jc * 1024 + it * 256 + tid;
        float xc[64];
#pragma unroll
        for (int c = 0; c < 64; ++c) xc[c] = xb[(size_t)c * NTOK + n];
        for (int co = 0; co < 64; ++co) {
            float acc = bo[co];
            const float4* mrow = reinterpret_cast<const float4*>(Ms + co * 64);
#pragma unroll
            for (int c4 = 0; c4 < 16; ++c4) {
                float4 m = mrow[c4];
                acc = fmaf(m.x, xc[4*c4+0], acc);
                acc = fmaf(m.y, xc[4*c4+1], acc);
                acc = fmaf(m.z, xc[4*c4+2], acc);
                acc = fmaf(m.w, xc[4*c4+3], acc);
            }
            ob[(size_t)co * NTOK + n] = acc;
        }
    }
}

extern "C" void kernel_launch(void* const* d_in, const int* in_sizes, int n_in,
                              void* d_out, int out_size)
{
    const float* x    = (const float*)d_in[0];
    const float* wqkv = (const float*)d_in[1];
    const float* wout = (const float*)d_in[2];
    const float* bout = (const float*)d_in[3];
    float* out = (float*)d_out;

    kv_ctx_kernel<<<BATCH * NCH, 128>>>(x, wqkv);
    reduce_proj_kernel<<<BATCH, 256>>>(wqkv, wout);
    out_proj_kernel<<<BATCH * CB, 256>>>(x, bout, out);
}